// round 2
// baseline (speedup 1.0000x reference)
#include <cuda_runtime.h>
#include <math_constants.h>

// Problem constants
#define L_OBS   512
#define NSEG    8192
#define BPOSE   8
#define NRAY    (BPOSE * L_OBS)          // 4096
#define FOV_F   6.283185307179586
#define EPS_PAR 0.0001f

#define PI_F    3.14159265358979323846f
#define TWOPI_F 6.28318530717958647692f
#define PAD_ANG 0.01f                     // conservative prefilter pad (radians)

// Buckets: 16 per pose, 32 beams each -> warp == bucket
#define NBKT_PP 16
#define NBKT    (BPOSE * NBKT_PP)        // 128
#define CHUNKS  16                        // chunk-warps per bucket list

// Static scratch (zero-initialized at module load)
__device__ float4   g_pk[BPOSE * NSEG];          // (sx, sy, dx, dy) per (pose, seg)
__device__ float    g_na[BPOSE * NSEG];          // num_a per (pose, seg)
__device__ int      g_iv[BPOSE * NSEG];          // packed beam window (k0 low16, width high16)
__device__ float4   g_lpk[NBKT * NSEG];          // per-bucket compacted segment data
__device__ float    g_lna[NBKT * NSEG];
__device__ int      g_cnt[NBKT];
__device__ unsigned g_best[NRAY];                // ~float_bits(min u); 0 == empty (self-resetting)

// ---------------------------------------------------------------- K1: prep
__global__ __launch_bounds__(256)
void prep_kernel(const float4* __restrict__ seg, const float* __restrict__ pose)
{
    const int id = blockIdx.x * 256 + threadIdx.x;   // 65536 = 8 * 8192
    const int b  = id >> 13;
    const int s  = id & (NSEG - 1);

    const float px = pose[b * 3 + 0];
    const float py = pose[b * 3 + 1];
    const float th = pose[b * 3 + 2];

    float4 q = seg[s];
    float sx = q.z - q.x;
    float sy = q.w - q.y;
    float dx = px - q.x;      // x1 - x3
    float dy = py - q.y;      // y1 - y3

    g_pk[b * NSEG + s] = make_float4(sx, sy, dx, dy);
    g_na[b * NSEG + s] = sx * dy - sy * dx;

    // Endpoint direction angles (from pose): v3 = (-dx,-dy), v4 = (sx-dx, sy-dy)
    float a3 = atan2f(-dy, -dx);
    float a4 = atan2f(sy - dy, sx - dx);
    float d  = a4 - a3;
    if (d >  PI_F) d -= TWOPI_F;
    if (d < -PI_F) d += TWOPI_F;
    float lo   = (d >= 0.0f) ? a3 : a4;
    float span = fabsf(d);

    // Beam-relative angle, normalized to [0, 2pi)
    float phi = lo - th;
    if (phi < 0.0f) phi += TWOPI_F;
    if (phi < 0.0f) phi += TWOPI_F;

    const float invD = (float)((double)L_OBS / FOV_F);
    int k0 = (int)ceilf ((phi - PAD_ANG) * invD);
    int k1 = (int)floorf((phi + span + PAD_ANG) * invD);
    int w  = k1 - k0;
    w = (w < 0) ? 0 : (w > 511 ? 511 : w);

    g_iv[b * NSEG + s] = (k0 & 0xffff) | (w << 16);
}

// ---------------------------------------------------------------- K2: build lists
__global__ __launch_bounds__(256)
void build_kernel()
{
    const int bkt  = blockIdx.x;            // 0..127
    const int pose = bkt >> 4;
    const int b0   = (bkt & (NBKT_PP - 1)) * 32;   // first beam of bucket
    const int lane = threadIdx.x & 31;

    __shared__ int s_cnt;
    if (threadIdx.x == 0) s_cnt = 0;
    __syncthreads();

    #pragma unroll 2
    for (int i = 0; i < NSEG; i += 256) {
        int s  = i + threadIdx.x;
        int iv = g_iv[pose * NSEG + s];
        int w  = iv >> 16;
        int k0 = iv & 511;
        // circular interval [k0, k0+w] vs [b0, b0+31] overlap
        bool pass = (((b0 - k0) & 511) <= w) || (((k0 - b0) & 511) <= 31);

        unsigned m = __ballot_sync(0xffffffffu, pass);
        if (m) {
            int leader = __ffs(m) - 1;
            int base = 0;
            if (lane == leader) base = atomicAdd(&s_cnt, __popc(m));
            base = __shfl_sync(0xffffffffu, base, leader);
            if (pass) {
                int pos = base + __popc(m & ((1u << lane) - 1u));
                g_lpk[bkt * NSEG + pos] = g_pk[pose * NSEG + s];
                g_lna[bkt * NSEG + pos] = g_na[pose * NSEG + s];
            }
        }
    }
    __syncthreads();
    if (threadIdx.x == 0) g_cnt[bkt] = s_cnt;
}

// ---------------------------------------------------------------- K3: raycast
__global__ __launch_bounds__(256)
void raycast_kernel(const float* __restrict__ pose)
{
    const int gw    = blockIdx.x * 8 + (threadIdx.x >> 5);  // global warp id
    const int bkt   = gw >> 4;                              // /CHUNKS
    const int chunk = gw & (CHUNKS - 1);
    const int pz    = bkt >> 4;
    const int lane  = threadIdx.x & 31;
    const int beam  = (bkt & (NBKT_PP - 1)) * 32 + lane;

    const float th = pose[pz * 3 + 2];
    const float kstep = (float)(FOV_F / (double)L_OBS);
    const float ang = (float)beam * kstep + th;
    const float rx = cosf(ang);
    const float ry = sinf(ang);

    const int n  = g_cnt[bkt];
    const int lo = (n * chunk) >> 4;
    const int hi = (n * (chunk + 1)) >> 4;

    const float4* __restrict__ lp = g_lpk + bkt * NSEG;
    const float*  __restrict__ ln = g_lna + bkt * NSEG;

    float best_na = CUDART_INF_F;
    float best_a  = 1.0f;

    #pragma unroll 4
    for (int j = lo; j < hi; ++j) {
        float4 p  = lp[j];           // broadcast LDG.128
        float nai = ln[j];
        float nb  = rx * p.w - ry * p.z;       // num_b
        float rxs = p.y * rx - p.x * ry;
        float absa  = fabsf(rxs);
        float absna = fabsf(nai);
        // valid <=> |rxs|>=eps, u_b=nb/rxs in [0,1], u_a=nai/rxs >= 0
        bool valid = (absa >= EPS_PAR) & (nb * rxs >= 0.0f)
                   & (fabsf(nb) <= absa) & (nai * rxs >= 0.0f);
        // cand u = absna/absa beats best iff absna*best_a < best_na*absa
        if (valid && (absna * best_a < best_na * absa)) {
            best_na = absna;
            best_a  = absa;
        }
    }

    float u = best_na / best_a;      // inf if no valid candidate
    atomicMax(&g_best[pz * L_OBS + beam], ~__float_as_uint(u));
}

// ---------------------------------------------------------------- K4: finalize
__global__ __launch_bounds__(256)
void finalize_kernel(const float4* __restrict__ seg,
                     const float*  __restrict__ pose,
                     float*        __restrict__ out)
{
    const int ray  = blockIdx.x * 256 + threadIdx.x;
    const int b    = ray >> 9;
    const int beam = ray & (L_OBS - 1);

    unsigned key = g_best[ray];
    g_best[ray] = 0u;                 // self-reset for next launch/replay
    float u = __uint_as_float(~key);

    const float px = pose[b * 3 + 0];
    const float py = pose[b * 3 + 1];
    const float th = pose[b * 3 + 2];

    const float kstep = (float)(FOV_F / (double)L_OBS);
    const float ang = (float)beam * kstep + th;
    const float rx = cosf(ang);
    const float ry = sinf(ang);

    if (isinf(u)) {
        // Reference: argmin over all-inf returns idx 0 -> u_a[0] (parallel -> 0)
        float4 q = seg[0];
        float sx = q.z - q.x;
        float sy = q.w - q.y;
        float dx = px - q.x;
        float dy = py - q.y;
        float num_a = sx * dy - sy * dx;
        float rxs   = sy * rx - sx * ry;
        u = (fabsf(rxs) < EPS_PAR) ? 0.0f : (num_a / rxs);
    }

    const float ix = px + rx * u;
    const float iy = py + ry * u;

    const int gi = ray * 2;
    out[gi + 0] = ix;
    out[gi + 1] = iy;

    const float c = cosf(th);
    const float s = sinf(th);
    const float ddx = ix - px;
    const float ddy = iy - py;
    out[NRAY * 2 + gi + 0] =  ddx * c + ddy * s;
    out[NRAY * 2 + gi + 1] = -ddx * s + ddy * c;
}

extern "C" void kernel_launch(void* const* d_in, const int* in_sizes, int n_in,
                              void* d_out, int out_size)
{
    const float4* seg  = (const float4*)d_in[0];   // line_seg [8192, 4]
    const float*  pose = (const float*)d_in[1];    // pose [8, 3]
    float* out = (float*)d_out;

    prep_kernel    <<<BPOSE * NSEG / 256, 256>>>(seg, pose);
    build_kernel   <<<NBKT, 256>>>();
    raycast_kernel <<<NBKT * CHUNKS / 8, 256>>>(pose);
    finalize_kernel<<<NRAY / 256, 256>>>(seg, pose, out);
}

// round 4
// speedup vs baseline: 3.0234x; 3.0234x over previous
#include <cuda_runtime.h>
#include <math_constants.h>

// Problem constants
#define L_OBS   512
#define NSEG    8192
#define BPOSE   8
#define NRAY    (BPOSE * L_OBS)          // 4096
#define FOV_F   6.283185307179586
#define EPS_PAR 0.0001f

#define PI_F    3.14159265358979323846f
#define TWOPI_F 6.28318530717958647692f
#define PAD_ANG 0.01f                     // conservative prefilter pad (radians)

// Buckets: 16 per pose, 32 beams each -> warp covers one bucket's beams
#define NBKT_PP 16
#define NBKT    (BPOSE * NBKT_PP)        // 128
#define SCH     8                         // segment chunks (1024 segs each)
#define CHSEG   (NSEG / SCH)              // 1024
#define TILE    256                       // segs per smem tile

// Static scratch (zero-initialized at module load)
__device__ int      g_iv[BPOSE * NSEG];   // packed beam window (k0 low16, width high16)
__device__ unsigned g_best[NRAY];         // ~float_bits(min u); 0 == empty (self-resetting)

// ---------------------------------------------------------------- K1: intervals
__global__ __launch_bounds__(256)
void prep_kernel(const float4* __restrict__ seg, const float* __restrict__ pose)
{
    const int id = blockIdx.x * 256 + threadIdx.x;   // 65536 = 8 * 8192
    const int b  = id >> 13;
    const int s  = id & (NSEG - 1);

    const float px = pose[b * 3 + 0];
    const float py = pose[b * 3 + 1];
    const float th = pose[b * 3 + 2];

    float4 q = seg[s];
    float sx = q.z - q.x;
    float sy = q.w - q.y;
    float dx = px - q.x;      // x1 - x3
    float dy = py - q.y;      // y1 - y3

    // Endpoint direction angles (from pose): v3 = (-dx,-dy), v4 = (sx-dx, sy-dy)
    float a3 = atan2f(-dy, -dx);
    float a4 = atan2f(sy - dy, sx - dx);
    float d  = a4 - a3;
    if (d >  PI_F) d -= TWOPI_F;
    if (d < -PI_F) d += TWOPI_F;
    float lo   = (d >= 0.0f) ? a3 : a4;
    float span = fabsf(d);

    float phi = lo - th;                   // beam-relative angle
    if (phi < 0.0f) phi += TWOPI_F;
    if (phi < 0.0f) phi += TWOPI_F;

    const float invD = (float)((double)L_OBS / FOV_F);
    int k0 = (int)ceilf ((phi - PAD_ANG) * invD);
    int k1 = (int)floorf((phi + span + PAD_ANG) * invD);
    int w  = k1 - k0;
    w = (w < 0) ? 0 : (w > 511 ? 511 : w);

    g_iv[b * NSEG + s] = (k0 & 0xffff) | (w << 16);
}

// ---------------------------------------------------------------- K2: main
__global__ __launch_bounds__(256)
void raycast_kernel(const float4* __restrict__ seg, const float* __restrict__ pose)
{
    const int bkt  = blockIdx.y;                 // 0..127
    const int pz   = bkt >> 4;
    const int b0   = (bkt & (NBKT_PP - 1)) * 32; // first beam of bucket
    const int tid  = threadIdx.x;
    const int wid  = tid >> 5;
    const int lane = tid & 31;

    __shared__ float4 s_pk[TILE];   // (sx, sy, dx, dy)
    __shared__ float  s_na[TILE];   // num_a
    __shared__ int    s_cnt;
    __shared__ float  s_rna[8][32];
    __shared__ float  s_ra [8][32];

    const float px = pose[pz * 3 + 0];
    const float py = pose[pz * 3 + 1];
    const float th = pose[pz * 3 + 2];

    // This lane's beam direction
    const float kstep = (float)(FOV_F / (double)L_OBS);
    const float ang = (float)(b0 + lane) * kstep + th;
    const float rx = cosf(ang);
    const float ry = sinf(ang);

    float best_na = CUDART_INF_F;
    float best_a  = 1.0f;

    const int* __restrict__ iv_base = g_iv + pz * NSEG + blockIdx.x * CHSEG;
    const float4* __restrict__ seg_base = seg + blockIdx.x * CHSEG;

    #pragma unroll 1
    for (int t = 0; t < CHSEG; t += TILE) {
        if (tid == 0) s_cnt = 0;
        __syncthreads();                    // also ends previous phase B

        // ---- phase A: prefilter + compact into smem
        {
            const int iv = iv_base[t + tid];
            const int w  = iv >> 16;
            const int k0 = iv & 511;
            // circular interval [k0, k0+w] vs [b0, b0+31]
            bool pass = (((b0 - k0) & 511) <= w) || (((k0 - b0) & 511) <= 31);

            unsigned m = __ballot_sync(0xffffffffu, pass);
            if (m) {
                int leader = __ffs(m) - 1;
                int base = 0;
                if (lane == leader) base = atomicAdd(&s_cnt, __popc(m));
                base = __shfl_sync(0xffffffffu, base, leader);
                if (pass) {
                    int pos = base + __popc(m & ((1u << lane) - 1u));
                    float4 q = seg_base[t + tid];
                    float sx = q.z - q.x;
                    float sy = q.w - q.y;
                    float dx = px - q.x;
                    float dy = py - q.y;
                    s_pk[pos] = make_float4(sx, sy, dx, dy);
                    s_na[pos] = sx * dy - sy * dx;
                }
            }
        }
        __syncthreads();

        // ---- phase B: exact test, warps split the compacted list
        const int m2 = s_cnt;
        for (int j = wid; j < m2; j += 8) {
            float4 p  = s_pk[j];            // broadcast LDS.128
            float nai = s_na[j];
            float nb  = rx * p.w - ry * p.z;       // num_b
            float rxs = p.y * rx - p.x * ry;
            float absa  = fabsf(rxs);
            float absna = fabsf(nai);
            // valid <=> |rxs|>=eps, u_b = nb/rxs in [0,1], u_a = nai/rxs >= 0
            bool valid = (absa >= EPS_PAR) & (nb * rxs >= 0.0f)
                       & (fabsf(nb) <= absa) & (nai * rxs >= 0.0f);
            // cand u = absna/absa beats best iff absna*best_a < best_na*absa
            if (valid && (absna * best_a < best_na * absa)) {
                best_na = absna;
                best_a  = absa;
            }
        }
    }

    // ---- block reduction across the 8 warps, then one atomic per beam
    s_rna[wid][lane] = best_na;
    s_ra [wid][lane] = best_a;
    __syncthreads();
    if (wid == 0) {
        float bn = s_rna[0][lane];
        float ba = s_ra [0][lane];
        #pragma unroll
        for (int w = 1; w < 8; ++w) {
            float n2 = s_rna[w][lane];
            float a2 = s_ra [w][lane];
            if (n2 * ba < bn * a2) { bn = n2; ba = a2; }
        }
        float u = bn / ba;                  // inf if nothing valid in this block
        atomicMax(&g_best[pz * L_OBS + b0 + lane], ~__float_as_uint(u));
    }
}

// ---------------------------------------------------------------- K3: finalize
__global__ __launch_bounds__(256)
void finalize_kernel(const float4* __restrict__ seg,
                     const float*  __restrict__ pose,
                     float*        __restrict__ out)
{
    const int ray  = blockIdx.x * 256 + threadIdx.x;
    const int b    = ray >> 9;
    const int beam = ray & (L_OBS - 1);

    unsigned key = g_best[ray];
    g_best[ray] = 0u;                 // self-reset for next launch/replay
    float u = __uint_as_float(~key);

    const float px = pose[b * 3 + 0];
    const float py = pose[b * 3 + 1];
    const float th = pose[b * 3 + 2];

    const float kstep = (float)(FOV_F / (double)L_OBS);
    const float ang = (float)beam * kstep + th;
    const float rx = cosf(ang);
    const float ry = sinf(ang);

    if (isinf(u)) {
        // Reference: argmin over all-inf returns idx 0 -> u_a[0] (parallel -> 0)
        float4 q = seg[0];
        float sx = q.z - q.x;
        float sy = q.w - q.y;
        float dx = px - q.x;
        float dy = py - q.y;
        float num_a = sx * dy - sy * dx;
        float rxs   = sy * rx - sx * ry;
        u = (fabsf(rxs) < EPS_PAR) ? 0.0f : (num_a / rxs);
    }

    const float ix = px + rx * u;
    const float iy = py + ry * u;

    const int gi = ray * 2;
    out[gi + 0] = ix;
    out[gi + 1] = iy;

    const float c = cosf(th);
    const float s = sinf(th);
    const float ddx = ix - px;
    const float ddy = iy - py;
    out[NRAY * 2 + gi + 0] =  ddx * c + ddy * s;
    out[NRAY * 2 + gi + 1] = -ddx * s + ddy * c;
}

extern "C" void kernel_launch(void* const* d_in, const int* in_sizes, int n_in,
                              void* d_out, int out_size)
{
    const float4* seg  = (const float4*)d_in[0];   // line_seg [8192, 4]
    const float*  pose = (const float*)d_in[1];    // pose [8, 3]
    float* out = (float*)d_out;

    prep_kernel    <<<BPOSE * NSEG / 256, 256>>>(seg, pose);
    dim3 g2(SCH, NBKT);
    raycast_kernel <<<g2, 256>>>(seg, pose);
    finalize_kernel<<<NRAY / 256, 256>>>(seg, pose, out);
}

// round 5
// speedup vs baseline: 3.2904x; 1.0883x over previous
#include <cuda_runtime.h>
#include <math_constants.h>

// Problem constants
#define L_OBS   512
#define NSEG    8192
#define BPOSE   8
#define NRAY    (BPOSE * L_OBS)          // 4096
#define FOV_F   6.283185307179586
#define EPS_PAR 0.0001f
#define PAD_ANG 0.01f                     // conservative cone pad (radians)

// Buckets: 16 per pose, 32 beams each -> warp lane == beam within bucket
#define NBKT_PP 16
#define NBKT    (BPOSE * NBKT_PP)        // 128
#define SCH     8                         // segment chunks (1024 segs each)
#define CHSEG   (NSEG / SCH)              // 1024
#define TILE    256                       // segs per smem tile

// Static scratch (zero-initialized at module load; self-resetting each launch)
__device__ unsigned g_best[NRAY];         // ~float_bits(min u); reset via atomicExch
__device__ int      g_done[NBKT];         // per-bucket completion counter

__global__ __launch_bounds__(256)
void raycast_kernel(const float4* __restrict__ seg, const float* __restrict__ pose,
                    float* __restrict__ out)
{
    const int bkt  = blockIdx.y;                 // 0..127
    const int pz   = bkt >> 4;
    const int b0   = (bkt & (NBKT_PP - 1)) * 32; // first beam of bucket
    const int tid  = threadIdx.x;
    const int wid  = tid >> 5;
    const int lane = tid & 31;

    __shared__ float4 s_pk[TILE];   // (sx, sy, dx, dy)
    __shared__ float  s_na[TILE];   // num_a
    __shared__ int    s_cnt;
    __shared__ float  s_rna[8][32];
    __shared__ float  s_ra [8][32];

    const float px = pose[pz * 3 + 0];
    const float py = pose[pz * 3 + 1];
    const float th = pose[pz * 3 + 2];

    const float kstep = (float)(FOV_F / (double)L_OBS);

    // Padded bucket cone edge directions (uniform across block)
    const float ang0 = (float)b0 * kstep + th - PAD_ANG;
    const float ang1 = (float)(b0 + 31) * kstep + th + PAD_ANG;
    const float e0x = cosf(ang0), e0y = sinf(ang0);
    const float e1x = cosf(ang1), e1y = sinf(ang1);

    // This lane's beam direction (for phase B)
    const float ang = (float)(b0 + lane) * kstep + th;
    const float rx = cosf(ang);
    const float ry = sinf(ang);

    float best_na = CUDART_INF_F;
    float best_a  = 1.0f;

    const float4* __restrict__ seg_base = seg + blockIdx.x * CHSEG;

    #pragma unroll 1
    for (int t = 0; t < CHSEG; t += TILE) {
        if (tid == 0) s_cnt = 0;
        __syncthreads();                    // also ends previous phase B

        // ---- phase A: cone-vs-wedge prefilter + compact into smem
        {
            float4 q = seg_base[t + tid];
            float dx = px - q.x;            // x1 - x3
            float dy = py - q.y;
            float sx = q.z - q.x;
            float sy = q.w - q.y;
            // Endpoint direction vectors from pose
            float v3x = -dx,        v3y = -dy;
            float v4x = q.z - px,   v4y = q.w - py;

            float t1 = v3x * v4y, t2 = v3y * v4x;
            float cz = t1 - t2;             // orientation of wedge [v3,v4]
            bool  pos = cz >= 0.0f;
            float ax = pos ? v3x : v4x,  ay = pos ? v3y : v4y;   // CCW start
            float bx = pos ? v4x : v3x,  by = pos ? v4y : v3y;   // CCW end

            // Arc intersection (both arcs < pi): a in cone  OR  e0 in wedge
            float c_ae0 = ax * e0y - ay * e0x;   //  cross(a,e0)
            float c_ae1 = ax * e1y - ay * e1x;   //  cross(a,e1)
            float c_e0b = e0x * by - e0y * bx;   //  cross(e0,b)
            bool in_cone  = (c_ae0 <= 0.0f) & (c_ae1 >= 0.0f);
            bool in_wedge = (c_ae0 >= 0.0f) & (c_e0b >= 0.0f);
            // near-degenerate wedge (pose ~collinear with segment): be conservative
            bool degen = fabsf(cz) <= 1e-4f * (fabsf(t1) + fabsf(t2));
            bool pass = in_cone | in_wedge | degen;

            unsigned m = __ballot_sync(0xffffffffu, pass);
            if (m) {
                int leader = __ffs(m) - 1;
                int base = 0;
                if (lane == leader) base = atomicAdd(&s_cnt, __popc(m));
                base = __shfl_sync(0xffffffffu, base, leader);
                if (pass) {
                    int p = base + __popc(m & ((1u << lane) - 1u));
                    s_pk[p] = make_float4(sx, sy, dx, dy);
                    s_na[p] = sx * dy - sy * dx;     // num_a (reference formula)
                }
            }
        }
        __syncthreads();

        // ---- phase B: exact test, warps split the compacted list
        const int m2 = s_cnt;
        for (int j = wid; j < m2; j += 8) {
            float4 p  = s_pk[j];            // broadcast LDS.128
            float nai = s_na[j];
            float nb  = rx * p.w - ry * p.z;       // num_b
            float rxs = p.y * rx - p.x * ry;
            float absa  = fabsf(rxs);
            float absna = fabsf(nai);
            // valid <=> |rxs|>=eps, u_b = nb/rxs in [0,1], u_a = nai/rxs >= 0
            bool valid = (absa >= EPS_PAR) & (nb * rxs >= 0.0f)
                       & (fabsf(nb) <= absa) & (nai * rxs >= 0.0f);
            // cand u = absna/absa beats best iff absna*best_a < best_na*absa
            if (valid && (absna * best_a < best_na * absa)) {
                best_na = absna;
                best_a  = absa;
            }
        }
    }

    // ---- block reduction across the 8 warps, one atomic per beam
    s_rna[wid][lane] = best_na;
    s_ra [wid][lane] = best_a;
    __syncthreads();
    if (wid != 0) return;

    float bn = s_rna[0][lane];
    float ba = s_ra [0][lane];
    #pragma unroll
    for (int w = 1; w < 8; ++w) {
        float n2 = s_rna[w][lane];
        float a2 = s_ra [w][lane];
        if (n2 * ba < bn * a2) { bn = n2; ba = a2; }
    }
    const int ray = pz * L_OBS + b0 + lane;
    float ublk = bn / ba;                   // inf if nothing valid in this block
    atomicMax(&g_best[ray], ~__float_as_uint(ublk));

    // ---- last block of this bucket finalizes its 32 beams
    __syncwarp();
    int last = 0;
    if (lane == 0) {
        __threadfence();
        last = (atomicAdd(&g_done[bkt], 1) == SCH - 1) ? 1 : 0;
    }
    last = __shfl_sync(0xffffffffu, last, 0);
    if (!last) return;
    __threadfence();

    unsigned key = atomicExch(&g_best[ray], 0u);   // read + reset for next launch
    float u = __uint_as_float(~key);

    if (__any_sync(0xffffffffu, isinf(u))) {
        // Reference: argmin over all-inf returns idx 0 -> u_a[0] (parallel -> 0)
        float4 q = seg[0];
        float sx = q.z - q.x;
        float sy = q.w - q.y;
        float dx = px - q.x;
        float dy = py - q.y;
        float num_a = sx * dy - sy * dx;
        float rxs   = sy * rx - sx * ry;
        float ufb = (fabsf(rxs) < EPS_PAR) ? 0.0f : (num_a / rxs);
        if (isinf(u)) u = ufb;
    }

    const float ix = px + rx * u;
    const float iy = py + ry * u;

    const int gi = ray * 2;
    out[gi + 0] = ix;
    out[gi + 1] = iy;

    const float c = cosf(th);
    const float s = sinf(th);
    const float ddx = ix - px;
    const float ddy = iy - py;
    out[NRAY * 2 + gi + 0] =  ddx * c + ddy * s;
    out[NRAY * 2 + gi + 1] = -ddx * s + ddy * c;

    if (lane == 0) g_done[bkt] = 0;        // reset for next launch/replay
}

extern "C" void kernel_launch(void* const* d_in, const int* in_sizes, int n_in,
                              void* d_out, int out_size)
{
    const float4* seg  = (const float4*)d_in[0];   // line_seg [8192, 4]
    const float*  pose = (const float*)d_in[1];    // pose [8, 3]
    float* out = (float*)d_out;

    dim3 g(SCH, NBKT);
    raycast_kernel<<<g, 256>>>(seg, pose, out);
}

// round 8
// speedup vs baseline: 4.5983x; 1.3975x over previous
#include <cuda_runtime.h>
#include <math_constants.h>

// Problem constants
#define L_OBS   512
#define NSEG    8192
#define BPOSE   8
#define NRAY    (BPOSE * L_OBS)          // 4096
#define FOV_F   6.283185307179586
#define EPS_PAR 0.0001f

// Distance culling radius (map units). Any segment giving a valid hit at
// u <= RCUT has dist(pose, segment) <= RCUT (r is unit), so the subset is
// exact for all beams that resolve with u <= RCUT.
#define RCUT    8.0f
#define R2M     (RCUT * RCUT * 1.0012f)   // conservative margin >> fp32 slop

#define KCH     8                         // list chunks in raycast kernel
#define MAXCH   (NSEG / KCH)              // 1024 (worst-case chunk size)

// Static scratch (zero-initialized at module load)
__device__ float4   g_lpk[BPOSE * NSEG];  // per-pose compacted (sx, sy, dx, dy)
__device__ float    g_lna[BPOSE * NSEG];  // per-pose compacted num_a
__device__ int      g_cnt[BPOSE];         // list sizes    (zeroed every launch)
__device__ unsigned g_best[NRAY];         // ~bits(min u)  (atomicExch self-reset)
__device__ int      g_done[BPOSE];        // chunk counter (zeroed every launch)

// ---------------------------------------------------------------- K0: reset
// Unconditional per-launch reset: no launch depends on the previous launch
// having completed its finalizer (robust to interrupted runs).
__global__ void reset_kernel()
{
    if (threadIdx.x < BPOSE) {
        g_cnt[threadIdx.x]  = 0;
        g_done[threadIdx.x] = 0;
    }
}

// ---------------------------------------------------------------- K1: build
__global__ __launch_bounds__(256)
void build_kernel(const float4* __restrict__ seg, const float* __restrict__ pose)
{
    const int id = blockIdx.x * 256 + threadIdx.x;   // 65536 = 8 * 8192
    const int b  = id >> 13;                         // warp-uniform (8192 % 32 == 0)
    const int s  = id & (NSEG - 1);
    const int lane = threadIdx.x & 31;

    const float px = pose[b * 3 + 0];
    const float py = pose[b * 3 + 1];

    float4 q = seg[s];
    float sx = q.z - q.x;
    float sy = q.w - q.y;
    float dx = px - q.x;      // AP = P - A
    float dy = py - q.y;

    // point-to-segment squared distance <= R2M, division-free
    float c    = dx * sx + dy * sy;          // dot(AP, S)
    float s2   = sx * sx + sy * sy;          // |S|^2
    float apsq = dx * dx + dy * dy;
    float bx = dx - sx, by = dy - sy;        // BP = P - B
    float bpsq = bx * bx + by * by;
    bool pass;
    if (c <= 0.0f)      pass = apsq <= R2M;
    else if (c >= s2)   pass = bpsq <= R2M;
    else                pass = (apsq * s2 - c * c) <= R2M * s2;

    unsigned m = __ballot_sync(0xffffffffu, pass);
    if (m) {
        int leader = __ffs(m) - 1;
        int base = 0;
        if (lane == leader) base = atomicAdd(&g_cnt[b], __popc(m));
        base = __shfl_sync(0xffffffffu, base, leader);
        if (pass) {
            int p = base + __popc(m & ((1u << lane) - 1u));
            if (p < NSEG) {                          // defensive bound
                g_lpk[b * NSEG + p] = make_float4(sx, sy, dx, dy);
                g_lna[b * NSEG + p] = sx * dy - sy * dx;     // num_a
            }
        }
    }
}

// ---------------------------------------------------------------- K2: raycast
__global__ __launch_bounds__(512)
void raycast_kernel(const float4* __restrict__ seg, const float* __restrict__ pose,
                    float* __restrict__ out)
{
    const int pz    = blockIdx.x >> 3;
    const int chunk = blockIdx.x & (KCH - 1);
    const int tid   = threadIdx.x;               // tid == beam

    __shared__ float4 s_pk[MAXCH];
    __shared__ float  s_na[MAXCH];
    __shared__ int    s_last;

    int cnt = g_cnt[pz];
    if (cnt > NSEG) cnt = NSEG;                  // defensive clamp
    const int lo  = (cnt * chunk) / KCH;
    const int hi  = (cnt * (chunk + 1)) / KCH;
    int m = hi - lo;
    if (m > MAXCH) m = MAXCH;                    // defensive clamp

    // stage this chunk of the per-pose list into smem
    for (int i = tid; i < m; i += 512) {
        s_pk[i] = g_lpk[pz * NSEG + lo + i];
        s_na[i] = g_lna[pz * NSEG + lo + i];
    }
    __syncthreads();

    const float px = pose[pz * 3 + 0];
    const float py = pose[pz * 3 + 1];
    const float th = pose[pz * 3 + 2];

    const float kstep = (float)(FOV_F / (double)L_OBS);
    const float ang = (float)tid * kstep + th;
    const float rx = cosf(ang);
    const float ry = sinf(ang);

    float best_na = CUDART_INF_F;
    float best_a  = 1.0f;

    #pragma unroll 2
    for (int j = 0; j < m; ++j) {
        float4 p  = s_pk[j];                 // broadcast LDS.128
        float nai = s_na[j];
        float nb  = rx * p.w - ry * p.z;     // num_b
        float rxs = p.y * rx - p.x * ry;
        float absa  = fabsf(rxs);
        float absna = fabsf(nai);
        // valid <=> |rxs|>=eps, u_b = nb/rxs in [0,1], u_a = nai/rxs >= 0
        bool valid = (absa >= EPS_PAR) & (nb * rxs >= 0.0f)
                   & (fabsf(nb) <= absa) & (nai * rxs >= 0.0f);
        if (valid && (absna * best_a < best_na * absa)) {
            best_na = absna;
            best_a  = absa;
        }
    }

    const int ray = pz * L_OBS + tid;
    float ublk = best_na / best_a;           // inf if nothing valid in chunk
    atomicMax(&g_best[ray], ~__float_as_uint(ublk));

    // ---- last chunk-block of this pose finalizes its 512 beams
    __syncthreads();
    if (tid == 0) {
        __threadfence();
        s_last = (atomicAdd(&g_done[pz], 1) == KCH - 1) ? 1 : 0;
    }
    __syncthreads();
    if (!s_last) return;
    __threadfence();

    unsigned key = atomicExch(&g_best[ray], 0u);   // read + reset for replay
    float u = __uint_as_float(~key);

    // Resolved iff u <= RCUT (any better segment would be in the subset).
    bool unres = !(u <= RCUT);                     // catches inf and > RCUT
    if (__any_sync(0xffffffffu, unres)) {
        // rare/adversarial path: exact full scan (reference semantics)
        float bn = CUDART_INF_F, ba = 1.0f;
        for (int j = 0; j < NSEG; ++j) {
            float4 q = __ldg(&seg[j]);
            float sx = q.z - q.x;
            float sy = q.w - q.y;
            float dx = px - q.x;
            float dy = py - q.y;
            float nai = sx * dy - sy * dx;
            float nb  = rx * dy - ry * dx;
            float rxs = sy * rx - sx * ry;
            float absa  = fabsf(rxs);
            float absna = fabsf(nai);
            bool valid = (absa >= EPS_PAR) & (nb * rxs >= 0.0f)
                       & (fabsf(nb) <= absa) & (nai * rxs >= 0.0f);
            if (valid && (absna * ba < bn * absa)) { bn = absna; ba = absa; }
        }
        float uf = bn / ba;
        if (isinf(uf)) {
            // Reference: argmin over all-inf returns idx 0 -> u_a[0] (parallel -> 0)
            float4 q = __ldg(&seg[0]);
            float sx = q.z - q.x;
            float sy = q.w - q.y;
            float dx = px - q.x;
            float dy = py - q.y;
            float num_a = sx * dy - sy * dx;
            float rxs   = sy * rx - sx * ry;
            uf = (fabsf(rxs) < EPS_PAR) ? 0.0f : (num_a / rxs);
        }
        if (unres) u = uf;
    }

    const float ix = px + rx * u;
    const float iy = py + ry * u;

    const int gi = ray * 2;
    out[gi + 0] = ix;
    out[gi + 1] = iy;

    const float c = cosf(th);
    const float s = sinf(th);
    const float ddx = ix - px;
    const float ddy = iy - py;
    out[NRAY * 2 + gi + 0] =  ddx * c + ddy * s;
    out[NRAY * 2 + gi + 1] = -ddx * s + ddy * c;
}

extern "C" void kernel_launch(void* const* d_in, const int* in_sizes, int n_in,
                              void* d_out, int out_size)
{
    const float4* seg  = (const float4*)d_in[0];   // line_seg [8192, 4]
    const float*  pose = (const float*)d_in[1];    // pose [8, 3]
    float* out = (float*)d_out;

    reset_kernel  <<<1, 32>>>();
    build_kernel  <<<BPOSE * NSEG / 256, 256>>>(seg, pose);
    raycast_kernel<<<BPOSE * KCH, 512>>>(seg, pose, out);
}

// round 10
// speedup vs baseline: 6.8474x; 1.4891x over previous
#include <cuda_runtime.h>
#include <math_constants.h>

// Problem constants
#define L_OBS   512
#define NSEG    8192
#define BPOSE   8
#define NRAY    (BPOSE * L_OBS)          // 4096
#define FOV_F   6.283185307179586
#define EPS_PAR 0.0001f

// Distance culling radius (map units). Any segment giving a valid hit at
// u <= RCUT has dist(pose, segment) <= RCUT (r is unit), so the culled set is
// exact for all beams that resolve with u <= RCUT. Beams that don't resolve
// within RCUT take the exact full-scan fallback below.
#define RCUT    8.0f
#define R2M     (RCUT * RCUT * 1.0012f)   // conservative margin >> fp32 slop

#define SCH     16                        // segment chunks per pose
#define CHSEG   (NSEG / SCH)              // 512 segs per chunk (1 per thread)
#define TPB     512                       // thread == beam

// Static scratch (zero-initialized at module load; self-resetting each launch)
__device__ unsigned g_best[NRAY];         // ~bits(min u); reset via atomicExch
__device__ int      g_done[BPOSE];        // chunk counter; reset by finalizer

__global__ __launch_bounds__(TPB)
void raycast_kernel(const float4* __restrict__ seg, const float* __restrict__ pose,
                    float* __restrict__ out)
{
    const int pz    = blockIdx.x >> 4;           // pose
    const int chunk = blockIdx.x & (SCH - 1);
    const int tid   = threadIdx.x;               // tid == beam
    const int lane  = tid & 31;

    __shared__ float4 s_pk[CHSEG];   // (sx, sy, dx, dy)
    __shared__ float  s_na[CHSEG];   // num_a
    __shared__ int    s_cnt;
    __shared__ int    s_last;

    if (tid == 0) s_cnt = 0;

    const float px = pose[pz * 3 + 0];
    const float py = pose[pz * 3 + 1];
    const float th = pose[pz * 3 + 2];
    __syncthreads();

    // ---- phase A: distance cull + compact into smem (1 segment per thread)
    {
        float4 q = seg[chunk * CHSEG + tid];
        float sx = q.z - q.x;
        float sy = q.w - q.y;
        float dx = px - q.x;      // AP = P - A
        float dy = py - q.y;

        // point-to-segment squared distance <= R2M, division-free
        float c    = dx * sx + dy * sy;          // dot(AP, S)
        float s2   = sx * sx + sy * sy;          // |S|^2
        float apsq = dx * dx + dy * dy;
        float bx = dx - sx, by = dy - sy;        // BP = P - B
        float bpsq = bx * bx + by * by;
        bool pass;
        if (c <= 0.0f)      pass = apsq <= R2M;
        else if (c >= s2)   pass = bpsq <= R2M;
        else                pass = (apsq * s2 - c * c) <= R2M * s2;

        unsigned m = __ballot_sync(0xffffffffu, pass);
        if (m) {
            int leader = __ffs(m) - 1;
            int base = 0;
            if (lane == leader) base = atomicAdd(&s_cnt, __popc(m));
            base = __shfl_sync(0xffffffffu, base, leader);
            if (pass) {
                int p = base + __popc(m & ((1u << lane) - 1u));
                s_pk[p] = make_float4(sx, sy, dx, dy);
                s_na[p] = sx * dy - sy * dx;     // num_a (reference formula)
            }
        }
    }
    __syncthreads();

    const float kstep = (float)(FOV_F / (double)L_OBS);
    const float ang = (float)tid * kstep + th;
    const float rx = cosf(ang);
    const float ry = sinf(ang);

    // ---- phase B: exact test over the compacted list (all beams, broadcast LDS)
    float best_na = CUDART_INF_F;
    float best_a  = 1.0f;
    const int m2 = s_cnt;

    #pragma unroll 2
    for (int j = 0; j < m2; ++j) {
        float4 p  = s_pk[j];
        float nai = s_na[j];
        float nb  = rx * p.w - ry * p.z;     // num_b
        float rxs = p.y * rx - p.x * ry;
        float absa  = fabsf(rxs);
        float absna = fabsf(nai);
        // valid <=> |rxs|>=eps, u_b = nb/rxs in [0,1], u_a = nai/rxs >= 0
        bool valid = (absa >= EPS_PAR) & (nb * rxs >= 0.0f)
                   & (fabsf(nb) <= absa) & (nai * rxs >= 0.0f);
        // cand u = absna/absa beats best iff absna*best_a < best_na*absa
        if (valid && (absna * best_a < best_na * absa)) {
            best_na = absna;
            best_a  = absa;
        }
    }

    const int ray = pz * L_OBS + tid;
    float ublk = best_na / best_a;           // inf if nothing valid in chunk
    atomicMax(&g_best[ray], ~__float_as_uint(ublk));

    // ---- last chunk-block of this pose finalizes its 512 beams
    __syncthreads();
    if (tid == 0) {
        __threadfence();
        s_last = (atomicAdd(&g_done[pz], 1) == SCH - 1) ? 1 : 0;
    }
    __syncthreads();
    if (!s_last) return;
    __threadfence();

    unsigned key = atomicExch(&g_best[ray], 0u);   // read + reset for replay
    float u = __uint_as_float(~key);

    // Resolved iff u <= RCUT (any better segment would have dist <= u <= RCUT
    // and thus be in the culled set). Otherwise: exact full scan.
    bool unres = !(u <= RCUT);                     // catches inf and > RCUT
    if (__any_sync(0xffffffffu, unres)) {
        float bn = CUDART_INF_F, ba = 1.0f;
        for (int j = 0; j < NSEG; ++j) {
            float4 q = __ldg(&seg[j]);
            float sx = q.z - q.x;
            float sy = q.w - q.y;
            float dx = px - q.x;
            float dy = py - q.y;
            float nai = sx * dy - sy * dx;
            float nb  = rx * dy - ry * dx;
            float rxs = sy * rx - sx * ry;
            float absa  = fabsf(rxs);
            float absna = fabsf(nai);
            bool valid = (absa >= EPS_PAR) & (nb * rxs >= 0.0f)
                       & (fabsf(nb) <= absa) & (nai * rxs >= 0.0f);
            if (valid && (absna * ba < bn * absa)) { bn = absna; ba = absa; }
        }
        float uf = bn / ba;
        if (isinf(uf)) {
            // Reference: argmin over all-inf returns idx 0 -> u_a[0] (parallel -> 0)
            float4 q = __ldg(&seg[0]);
            float sx = q.z - q.x;
            float sy = q.w - q.y;
            float dx = px - q.x;
            float dy = py - q.y;
            float num_a = sx * dy - sy * dx;
            float rxs   = sy * rx - sx * ry;
            uf = (fabsf(rxs) < EPS_PAR) ? 0.0f : (num_a / rxs);
        }
        if (unres) u = uf;
    }

    const float ix = px + rx * u;
    const float iy = py + ry * u;

    const int gi = ray * 2;
    out[gi + 0] = ix;
    out[gi + 1] = iy;

    const float c = cosf(th);
    const float s = sinf(th);
    const float ddx = ix - px;
    const float ddy = iy - py;
    out[NRAY * 2 + gi + 0] =  ddx * c + ddy * s;
    out[NRAY * 2 + gi + 1] = -ddx * s + ddy * c;

    if (tid == 0) g_done[pz] = 0;            // reset for next launch/replay
}

extern "C" void kernel_launch(void* const* d_in, const int* in_sizes, int n_in,
                              void* d_out, int out_size)
{
    const float4* seg  = (const float4*)d_in[0];   // line_seg [8192, 4]
    const float*  pose = (const float*)d_in[1];    // pose [8, 3]
    float* out = (float*)d_out;

    raycast_kernel<<<BPOSE * SCH, TPB>>>(seg, pose, out);
}